// round 2
// baseline (speedup 1.0000x reference)
#include <cuda_runtime.h>
#include <cuda_fp16.h>
#include <cstdint>

// Problem dims (fixed by the dataset)
#define M_DIM 8192
#define N_DIM 11008
#define K_DIM 4096

#define BM 128
#define BN 128
#define BK 32
#define STRIDE 40   // padded halves per smem row (32 + 8 pad) -> conflict-free ldmatrix

// fp16 scratch (static device globals: allocation-free per the harness rules)
__device__ __half g_XH[(size_t)M_DIM * K_DIM];   // 67 MB
__device__ __half g_WH[(size_t)N_DIM * K_DIM];   // 90 MB

// ---------------------------------------------------------------------------
// Pre-pass conversions
// ---------------------------------------------------------------------------
__global__ void cvt_x_kernel(const float* __restrict__ x) {
    size_t i = (size_t)blockIdx.x * blockDim.x + threadIdx.x;
    const size_t n4 = (size_t)M_DIM * K_DIM / 4;
    if (i < n4) {
        float4 v = reinterpret_cast<const float4*>(x)[i];
        __half2* o = reinterpret_cast<__half2*>(g_XH);
        o[2 * i]     = __floats2half2_rn(v.x, v.y);
        o[2 * i + 1] = __floats2half2_rn(v.z, v.w);
    }
}

// Weights arrive as int32 (harness promotes int8 -> int32).
__global__ void cvt_w_kernel(const int* __restrict__ w) {
    size_t i = (size_t)blockIdx.x * blockDim.x + threadIdx.x;
    const size_t n4 = (size_t)N_DIM * K_DIM / 4;
    if (i < n4) {
        int4 v = reinterpret_cast<const int4*>(w)[i];
        __half2* o = reinterpret_cast<__half2*>(g_WH);
        o[2 * i]     = __halves2half2(__int2half_rn(v.x), __int2half_rn(v.y));
        o[2 * i + 1] = __halves2half2(__int2half_rn(v.z), __int2half_rn(v.w));
    }
}

// ---------------------------------------------------------------------------
// PTX helpers
// ---------------------------------------------------------------------------
__device__ __forceinline__ uint32_t smem_u32(const void* p) {
    return (uint32_t)__cvta_generic_to_shared(p);
}

__device__ __forceinline__ void cp_async16(void* dst, const void* src) {
    uint32_t d = smem_u32(dst);
    asm volatile("cp.async.cg.shared.global [%0], [%1], 16;\n" :: "r"(d), "l"(src));
}
__device__ __forceinline__ void cp_commit() {
    asm volatile("cp.async.commit_group;\n" ::);
}
template <int Ngroups>
__device__ __forceinline__ void cp_wait() {
    asm volatile("cp.async.wait_group %0;\n" :: "n"(Ngroups));
}

__device__ __forceinline__ void ldsm_x4(uint32_t& r0, uint32_t& r1, uint32_t& r2, uint32_t& r3,
                                        uint32_t addr) {
    asm volatile("ldmatrix.sync.aligned.m8n8.x4.shared.b16 {%0,%1,%2,%3}, [%4];\n"
                 : "=r"(r0), "=r"(r1), "=r"(r2), "=r"(r3) : "r"(addr));
}
__device__ __forceinline__ void ldsm_x2(uint32_t& r0, uint32_t& r1, uint32_t addr) {
    asm volatile("ldmatrix.sync.aligned.m8n8.x2.shared.b16 {%0,%1}, [%2];\n"
                 : "=r"(r0), "=r"(r1) : "r"(addr));
}

__device__ __forceinline__ void mma16816(float& c0, float& c1, float& c2, float& c3,
                                         uint32_t a0, uint32_t a1, uint32_t a2, uint32_t a3,
                                         uint32_t b0, uint32_t b1) {
    asm volatile(
        "mma.sync.aligned.m16n8k16.row.col.f32.f16.f16.f32 "
        "{%0,%1,%2,%3}, {%4,%5,%6,%7}, {%8,%9}, {%0,%1,%2,%3};\n"
        : "+f"(c0), "+f"(c1), "+f"(c2), "+f"(c3)
        : "r"(a0), "r"(a1), "r"(a2), "r"(a3), "r"(b0), "r"(b1));
}

// ---------------------------------------------------------------------------
// GEMM: out[M,N] = scale * (XH[M,K] @ WH[N,K]^T) + bias[N]
// ---------------------------------------------------------------------------
__global__ void __launch_bounds__(256)
gemm_kernel(float* __restrict__ out, const float* __restrict__ scale_p,
            const float* __restrict__ bias) {
    __shared__ __align__(16) __half sA[2][BM][STRIDE];
    __shared__ __align__(16) __half sB[2][BN][STRIDE];

    const int tid  = threadIdx.x;
    const int lane = tid & 31;
    const int warp = tid >> 5;
    const int wm   = warp >> 2;  // 0..1  (64-row band)
    const int wn   = warp & 3;   // 0..3  (32-col band)

    // Supertile swizzle for L2 reuse: n-groups of 16, m fastest within group.
    const int MB = M_DIM / BM;   // 64
    const int NB = N_DIM / BN;   // 86
    const int GN = 16;
    int bid   = blockIdx.x;
    int group = bid / (MB * GN);
    int rem   = bid % (MB * GN);
    int n0    = group * GN;
    int width = (NB - n0 < GN) ? (NB - n0) : GN;
    int bm    = rem / width;
    int bn    = n0 + rem % width;

    const __half* gA = g_XH + (size_t)bm * BM * K_DIM;
    const __half* gB = g_WH + (size_t)bn * BN * K_DIM;

    float acc[4][4][4];
#pragma unroll
    for (int i = 0; i < 4; i++)
#pragma unroll
        for (int j = 0; j < 4; j++)
#pragma unroll
            for (int r = 0; r < 4; r++) acc[i][j][r] = 0.0f;

    const int NK = K_DIM / BK;  // 128

    // 512 16B-chunks per tile per operand; 256 threads x 2 iters
    auto load_stage = [&](int s, int ks) {
        const __half* a = gA + ks * BK;
        const __half* b = gB + ks * BK;
#pragma unroll
        for (int it = 0; it < 2; it++) {
            int c   = tid + it * 256;
            int row = c >> 2;
            int col = (c & 3) << 3;  // halves
            cp_async16(&sA[s][row][col], a + (size_t)row * K_DIM + col);
            cp_async16(&sB[s][row][col], b + (size_t)row * K_DIM + col);
        }
    };

    auto compute = [&](int s) {
#pragma unroll
        for (int kk = 0; kk < 2; kk++) {
            uint32_t a[4][4], b[4][2];
#pragma unroll
            for (int i = 0; i < 4; i++) {
                int row = wm * 64 + i * 16 + (lane & 15);
                int col = kk * 16 + (lane >> 4) * 8;
                ldsm_x4(a[i][0], a[i][1], a[i][2], a[i][3], smem_u32(&sA[s][row][col]));
            }
#pragma unroll
            for (int j = 0; j < 4; j++) {
                int row = wn * 32 + j * 8 + (lane & 7);
                int col = kk * 16 + ((lane >> 3) & 1) * 8;
                ldsm_x2(b[j][0], b[j][1], smem_u32(&sB[s][row][col]));
            }
#pragma unroll
            for (int i = 0; i < 4; i++)
#pragma unroll
                for (int j = 0; j < 4; j++)
                    mma16816(acc[i][j][0], acc[i][j][1], acc[i][j][2], acc[i][j][3],
                             a[i][0], a[i][1], a[i][2], a[i][3], b[j][0], b[j][1]);
        }
    };

    // Double-buffered mainloop
    load_stage(0, 0);
    cp_commit();
    for (int ks = 0; ks < NK; ks++) {
        if (ks + 1 < NK) {
            load_stage((ks + 1) & 1, ks + 1);
            cp_commit();
            cp_wait<1>();
        } else {
            cp_wait<0>();
        }
        __syncthreads();
        compute(ks & 1);
        __syncthreads();
    }

    // Epilogue: out = scale*acc + bias
    const float scale = __ldg(scale_p);
    const int m_base = bm * BM + wm * 64 + (lane >> 2);
    const int n_base = bn * BN + wn * 32 + (lane & 3) * 2;
#pragma unroll
    for (int i = 0; i < 4; i++) {
#pragma unroll
        for (int j = 0; j < 4; j++) {
            int m = m_base + i * 16;
            int n = n_base + j * 8;
            float2 bv = *reinterpret_cast<const float2*>(&bias[n]);
            float2 r0, r1;
            r0.x = acc[i][j][0] * scale + bv.x;
            r0.y = acc[i][j][1] * scale + bv.y;
            r1.x = acc[i][j][2] * scale + bv.x;
            r1.y = acc[i][j][3] * scale + bv.y;
            *reinterpret_cast<float2*>(&out[(size_t)m * N_DIM + n])       = r0;
            *reinterpret_cast<float2*>(&out[(size_t)(m + 8) * N_DIM + n]) = r1;
        }
    }
}

// ---------------------------------------------------------------------------
// Entry point (graph-capturable: kernel launches only)
// ---------------------------------------------------------------------------
extern "C" void kernel_launch(void* const* d_in, const int* in_sizes, int n_in,
                              void* d_out, int out_size) {
    const float* x     = (const float*)d_in[0];
    const int*   w     = (const int*)d_in[1];    // int8 promoted to int32 by harness
    const float* scale = (const float*)d_in[2];
    const float* bias  = (const float*)d_in[3];
    float*       out   = (float*)d_out;

    const size_t nx4 = (size_t)M_DIM * K_DIM / 4;
    cvt_x_kernel<<<(unsigned)((nx4 + 255) / 256), 256>>>(x);
    const size_t nw4 = (size_t)N_DIM * K_DIM / 4;
    cvt_w_kernel<<<(unsigned)((nw4 + 255) / 256), 256>>>(w);

    const int grid = (M_DIM / BM) * (N_DIM / BN);  // 5504
    gemm_kernel<<<grid, 256>>>(out, scale, bias);
}

// round 4
// speedup vs baseline: 1.0328x; 1.0328x over previous
#include <cuda_runtime.h>
#include <cuda_fp16.h>
#include <cstdint>

// Problem dims (fixed by the dataset)
#define M_DIM 8192
#define N_DIM 11008
#define K_DIM 4096

#define BM 128
#define BN 128
#define BK 64            // fp16 K elements per stage
#define STAGES 3
#define NKIT (K_DIM / BK)  // 64
#define SSTRIDE 72       // halves per smem row (64 + 8 pad) -> conflict-free ldmatrix

#define STAGE_HALVES (2 * BM * SSTRIDE)          // A + B per stage = 18432 halves
#define A_OFF 0
#define B_OFF (BM * SSTRIDE)                     // 9216 halves
#define SMEM_BYTES (STAGES * STAGE_HALVES * 2)   // 110592 B = 108 KB

// fp16 scratch (static device globals: allocation-free per the harness rules)
__device__ __half g_XH[(size_t)M_DIM * K_DIM];   // 67 MB
__device__ __half g_WH[(size_t)N_DIM * K_DIM];   // 90 MB

// ---------------------------------------------------------------------------
// Pre-pass conversions
// ---------------------------------------------------------------------------
__global__ void cvt_x_kernel(const float* __restrict__ x) {
    size_t i = (size_t)blockIdx.x * blockDim.x + threadIdx.x;
    const size_t n4 = (size_t)M_DIM * K_DIM / 4;
    if (i < n4) {
        float4 v = reinterpret_cast<const float4*>(x)[i];
        __half2* o = reinterpret_cast<__half2*>(g_XH);
        o[2 * i]     = __floats2half2_rn(v.x, v.y);
        o[2 * i + 1] = __floats2half2_rn(v.z, v.w);
    }
}

// Weights arrive as int32 (harness promotes int8 -> int32).
__global__ void cvt_w_kernel(const int* __restrict__ w) {
    size_t i = (size_t)blockIdx.x * blockDim.x + threadIdx.x;
    const size_t n4 = (size_t)N_DIM * K_DIM / 4;
    if (i < n4) {
        int4 v = reinterpret_cast<const int4*>(w)[i];
        __half2* o = reinterpret_cast<__half2*>(g_WH);
        o[2 * i]     = __halves2half2(__int2half_rn(v.x), __int2half_rn(v.y));
        o[2 * i + 1] = __halves2half2(__int2half_rn(v.z), __int2half_rn(v.w));
    }
}

// ---------------------------------------------------------------------------
// PTX helpers
// ---------------------------------------------------------------------------
__device__ __forceinline__ uint32_t smem_u32(const void* p) {
    return (uint32_t)__cvta_generic_to_shared(p);
}

__device__ __forceinline__ void cp_async16(uint32_t dst, const void* src) {
    asm volatile("cp.async.cg.shared.global [%0], [%1], 16;\n" :: "r"(dst), "l"(src));
}
__device__ __forceinline__ void cp_commit() {
    asm volatile("cp.async.commit_group;\n" ::);
}
template <int Ngroups>
__device__ __forceinline__ void cp_wait() {
    asm volatile("cp.async.wait_group %0;\n" :: "n"(Ngroups));
}

__device__ __forceinline__ void ldsm_x4(uint32_t& r0, uint32_t& r1, uint32_t& r2, uint32_t& r3,
                                        uint32_t addr) {
    asm volatile("ldmatrix.sync.aligned.m8n8.x4.shared.b16 {%0,%1,%2,%3}, [%4];\n"
                 : "=r"(r0), "=r"(r1), "=r"(r2), "=r"(r3) : "r"(addr));
}

__device__ __forceinline__ void mma16816(float& c0, float& c1, float& c2, float& c3,
                                         uint32_t a0, uint32_t a1, uint32_t a2, uint32_t a3,
                                         uint32_t b0, uint32_t b1) {
    asm volatile(
        "mma.sync.aligned.m16n8k16.row.col.f32.f16.f16.f32 "
        "{%0,%1,%2,%3}, {%4,%5,%6,%7}, {%8,%9}, {%0,%1,%2,%3};\n"
        : "+f"(c0), "+f"(c1), "+f"(c2), "+f"(c3)
        : "r"(a0), "r"(a1), "r"(a2), "r"(a3), "r"(b0), "r"(b1));
}

// ---------------------------------------------------------------------------
// GEMM: out[M,N] = scale * (XH[M,K] @ WH[N,K]^T) + bias[N]
// 3-stage cp.async pipeline, BK=64, one __syncthreads per iteration,
// 2 CTAs per SM (4 warps/SMSP) for latency hiding.
// ---------------------------------------------------------------------------
__global__ void __launch_bounds__(256, 2)
gemm_kernel(float* __restrict__ out, const float* __restrict__ scale_p,
            const float* __restrict__ bias) {
    extern __shared__ __align__(16) __half smem[];

    const int tid  = threadIdx.x;
    const int lane = tid & 31;
    const int warp = tid >> 5;
    const int wm   = warp >> 2;  // 0..1  (64-row band)
    const int wn   = warp & 3;   // 0..3  (32-col band)

    // Supertile swizzle for L2 reuse: n-groups of 16, m fastest within group.
    const int MB = M_DIM / BM;   // 64
    const int NB = N_DIM / BN;   // 86
    const int GN = 16;
    int bid   = blockIdx.x;
    int group = bid / (MB * GN);
    int rem   = bid % (MB * GN);
    int n0    = group * GN;
    int width = (NB - n0 < GN) ? (NB - n0) : GN;
    int bm    = rem / width;
    int bn    = n0 + rem % width;

    const __half* gA = g_XH + (size_t)bm * BM * K_DIM;
    const __half* gB = g_WH + (size_t)bn * BN * K_DIM;

    float acc[4][4][4];
#pragma unroll
    for (int i = 0; i < 4; i++)
#pragma unroll
        for (int j = 0; j < 4; j++)
#pragma unroll
            for (int r = 0; r < 4; r++) acc[i][j][r] = 0.0f;

    // Stage loader: A 128x64 + B 128x64 halves = 2048 16B chunks; 8 per thread.
    auto load_stage = [&](int s, int it) {
        __half* sA = smem + s * STAGE_HALVES + A_OFF;
        __half* sB = smem + s * STAGE_HALVES + B_OFF;
        const __half* a = gA + it * BK;
        const __half* b = gB + it * BK;
#pragma unroll
        for (int i = 0; i < 4; i++) {
            int c   = tid + i * 256;
            int row = c >> 3;
            int col = (c & 7) << 3;  // halves
            cp_async16(smem_u32(sA + row * SSTRIDE + col), a + (size_t)row * K_DIM + col);
        }
#pragma unroll
        for (int i = 0; i < 4; i++) {
            int c   = tid + i * 256;
            int row = c >> 3;
            int col = (c & 7) << 3;
            cp_async16(smem_u32(sB + row * SSTRIDE + col), b + (size_t)row * K_DIM + col);
        }
    };

    auto compute = [&](int s) {
        const __half* sA = smem + s * STAGE_HALVES + A_OFF;
        const __half* sB = smem + s * STAGE_HALVES + B_OFF;
#pragma unroll
        for (int kk = 0; kk < 4; kk++) {
            uint32_t a[4][4], bf[2][4];
#pragma unroll
            for (int i = 0; i < 4; i++) {
                int row = wm * 64 + i * 16 + (lane & 15);
                int col = kk * 16 + (lane >> 4) * 8;
                ldsm_x4(a[i][0], a[i][1], a[i][2], a[i][3],
                        smem_u32(sA + row * SSTRIDE + col));
            }
#pragma unroll
            for (int jp = 0; jp < 2; jp++) {
                int row = wn * 32 + jp * 16 + (lane & 15);
                int col = kk * 16 + (lane >> 4) * 8;
                // regs: r0=b0(j even), r1=b0(j odd), r2=b1(j even), r3=b1(j odd)
                ldsm_x4(bf[jp][0], bf[jp][1], bf[jp][2], bf[jp][3],
                        smem_u32(sB + row * SSTRIDE + col));
            }
#pragma unroll
            for (int i = 0; i < 4; i++)
#pragma unroll
                for (int j = 0; j < 4; j++) {
                    int jp = j >> 1, od = j & 1;
                    mma16816(acc[i][j][0], acc[i][j][1], acc[i][j][2], acc[i][j][3],
                             a[i][0], a[i][1], a[i][2], a[i][3],
                             bf[jp][od], bf[jp][2 + od]);
                }
        }
    };

    // Prologue: fill first 2 stages
    load_stage(0, 0);
    cp_commit();
    load_stage(1, 1);
    cp_commit();

    int slot = 0;
#pragma unroll 1
    for (int it = 0; it < NKIT; it++) {
        cp_wait<1>();       // stage 'it' loads complete (this thread)
        __syncthreads();    // complete CTA-wide; also protects slot reuse below
        int nslot = slot + 2;
        if (nslot >= STAGES) nslot -= STAGES;
        if (it + 2 < NKIT) load_stage(nslot, it + 2);
        cp_commit();        // uniform group accounting (possibly empty)
        compute(slot);
        if (++slot == STAGES) slot = 0;
    }

    // Epilogue: out = scale*acc + bias
    const float scale = __ldg(scale_p);
    const int m_base = bm * BM + wm * 64 + (lane >> 2);
    const int n_base = bn * BN + wn * 32 + (lane & 3) * 2;
#pragma unroll
    for (int i = 0; i < 4; i++) {
#pragma unroll
        for (int j = 0; j < 4; j++) {
            int m = m_base + i * 16;
            int n = n_base + j * 8;
            float2 bv = *reinterpret_cast<const float2*>(&bias[n]);
            float2 r0, r1;
            r0.x = acc[i][j][0] * scale + bv.x;
            r0.y = acc[i][j][1] * scale + bv.y;
            r1.x = acc[i][j][2] * scale + bv.x;
            r1.y = acc[i][j][3] * scale + bv.y;
            *reinterpret_cast<float2*>(&out[(size_t)m * N_DIM + n])       = r0;
            *reinterpret_cast<float2*>(&out[(size_t)(m + 8) * N_DIM + n]) = r1;
        }
    }
}

// ---------------------------------------------------------------------------
// Entry point (graph-capturable: kernel launches only)
// ---------------------------------------------------------------------------
extern "C" void kernel_launch(void* const* d_in, const int* in_sizes, int n_in,
                              void* d_out, int out_size) {
    const float* x     = (const float*)d_in[0];
    const int*   w     = (const int*)d_in[1];    // int8 promoted to int32 by harness
    const float* scale = (const float*)d_in[2];
    const float* bias  = (const float*)d_in[3];
    float*       out   = (float*)d_out;

    cudaFuncSetAttribute(gemm_kernel,
                         cudaFuncAttributeMaxDynamicSharedMemorySize, SMEM_BYTES);

    const size_t nx4 = (size_t)M_DIM * K_DIM / 4;
    cvt_x_kernel<<<(unsigned)((nx4 + 255) / 256), 256>>>(x);
    const size_t nw4 = (size_t)N_DIM * K_DIM / 4;
    cvt_w_kernel<<<(unsigned)((nw4 + 255) / 256), 256>>>(w);

    const int grid = (M_DIM / BM) * (N_DIM / BN);  // 5504
    gemm_kernel<<<grid, 256, SMEM_BYTES>>>(out, scale, bias);
}